// round 1
// baseline (speedup 1.0000x reference)
#include <cuda_runtime.h>
#include <cstdint>

// ---------------------------------------------------------------------------
// EarthAttention3D (Pangu-Weather window attention), fixed shapes:
//   B_=960 windows, L=144, C=192, HEADS=6, hd=32, NUM_WINDOWS=64, W_WINS=15
// Pipeline: K0 bias gather -> K1 QKV GEMM -> K2 fused attention -> K3 out GEMM
// All fp32 (baseline round).
// ---------------------------------------------------------------------------

#define NWIN   960
#define LTOK   144
#define CDIM   192
#define HEADS  6
#define HD     32
#define NW     64
#define WWINS  15
#define MTOT   (NWIN * LTOK)          // 138240
#define QK_SCALE 0.17677669529663687f // 32^-0.5

// Scratch (device globals; allocation is forbidden)
__device__ float g_Q[NWIN * HEADS * LTOK * HD];
__device__ float g_K[NWIN * HEADS * LTOK * HD];
__device__ float g_V[NWIN * HEADS * LTOK * HD];
__device__ float g_ctx[MTOT * CDIM];
__device__ float g_bias[NW * HEADS * LTOK * LTOK];

// ---------------------------------------------------------------------------
// K0: gather bias_table[position_index] -> g_bias[nw][h][l][m]
// ---------------------------------------------------------------------------
__global__ void bias_gather_kernel(const float* __restrict__ table,
                                   const int* __restrict__ pidx) {
    const int nwh = blockIdx.x;             // 0..383  (= nw*6 + h)
    const int nw = nwh / HEADS, h = nwh % HEADS;
    float* dst = g_bias + (size_t)nwh * (LTOK * LTOK);
    for (int i = threadIdx.x; i < LTOK * LTOK; i += blockDim.x) {
        int pi = pidx[i];
        dst[i] = table[((size_t)pi * NW + nw) * HEADS + h];
    }
}

// ---------------------------------------------------------------------------
// K1: qkv = x @ W1 + b1, scattered to head-major Q (scaled), K, V
//   A: (138240, 192) row-major   B: (192, 576) row-major
//   tile: 128(M) x 64(N) x 16(K), 256 threads, 8x4 per thread
// ---------------------------------------------------------------------------
__global__ __launch_bounds__(256) void qkv_gemm_kernel(
    const float* __restrict__ X, const float* __restrict__ W1,
    const float* __restrict__ b1) {
    __shared__ float As[16][132];   // transposed [k][m], padded
    __shared__ float Bs[16][64];

    const int tid = threadIdx.x;
    const int tx = tid & 15, ty = tid >> 4;
    const int m_blk = blockIdx.x * 128;
    const int n_blk = blockIdx.y * 64;

    float acc[8][4];
#pragma unroll
    for (int i = 0; i < 8; i++)
#pragma unroll
        for (int j = 0; j < 4; j++) acc[i][j] = 0.f;

    for (int k0 = 0; k0 < CDIM; k0 += 16) {
#pragma unroll
        for (int it = 0; it < 2; it++) {
            int lin = tid + it * 256;
            int row = lin >> 2;
            int cg = (lin & 3) * 4;
            float4 v = *reinterpret_cast<const float4*>(
                &X[(size_t)(m_blk + row) * CDIM + k0 + cg]);
            As[cg + 0][row] = v.x; As[cg + 1][row] = v.y;
            As[cg + 2][row] = v.z; As[cg + 3][row] = v.w;
        }
        {
            int row = tid >> 4;
            int cg = (tid & 15) * 4;
            *reinterpret_cast<float4*>(&Bs[row][cg]) =
                *reinterpret_cast<const float4*>(
                    &W1[(size_t)(k0 + row) * 576 + n_blk + cg]);
        }
        __syncthreads();
#pragma unroll
        for (int k = 0; k < 16; k++) {
            float4 a0 = *reinterpret_cast<const float4*>(&As[k][ty * 8]);
            float4 a1 = *reinterpret_cast<const float4*>(&As[k][ty * 8 + 4]);
            float4 bv = *reinterpret_cast<const float4*>(&Bs[k][tx * 4]);
            float a[8] = {a0.x, a0.y, a0.z, a0.w, a1.x, a1.y, a1.z, a1.w};
            float bb[4] = {bv.x, bv.y, bv.z, bv.w};
#pragma unroll
            for (int i = 0; i < 8; i++)
#pragma unroll
                for (int j = 0; j < 4; j++) acc[i][j] = fmaf(a[i], bb[j], acc[i][j]);
        }
        __syncthreads();
    }

    // epilogue: scatter into Q/K/V, head-major [b][h][l][d]
#pragma unroll
    for (int i = 0; i < 8; i++) {
        int m = m_blk + ty * 8 + i;
        int bi = m / LTOK, l = m % LTOK;
#pragma unroll
        for (int j = 0; j < 4; j++) {
            int col = n_blk + tx * 4 + j;
            float val = acc[i][j] + b1[col];
            int t = col / CDIM;
            int rem = col - t * CDIM;
            int h = rem >> 5, d = rem & 31;
            size_t dst = ((size_t)(bi * HEADS + h) * LTOK + l) * HD + d;
            if (t == 0)      g_Q[dst] = val * QK_SCALE;
            else if (t == 1) g_K[dst] = val;
            else             g_V[dst] = val;
        }
    }
}

// ---------------------------------------------------------------------------
// K2: fused attention per (window, head). 256 threads.
//   phase 1: 8 warps, 18 rows each (3 at a time): S = QK^T + bias + mask,
//            softmax -> P in SMEM
//   phase 2: register-tiled PV GEMM (144x32 = 256 threads * 9x2)
// ---------------------------------------------------------------------------
#define SKT_STRIDE 161
#define SP_STRIDE 145
#define SMEM_F (4608 + 32 * SKT_STRIDE + 4608 + LTOK * SP_STRIDE)
#define SMEM_BYTES (SMEM_F * 4)

__global__ __launch_bounds__(256) void attn_kernel(const float* __restrict__ mask) {
    extern __shared__ float sm[];
    float* sQ = sm;                               // [144][32]
    float* sKt = sm + 4608;                       // [32][161]
    float* sV = sKt + 32 * SKT_STRIDE;            // [144][32]
    float* sP = sV + 4608;                        // [144][145]

    const int bh = blockIdx.x;
    const int b = bh / HEADS, h = bh % HEADS;
    const int nw = b / WWINS;
    const int tid = threadIdx.x;
    const size_t base = (size_t)bh * (LTOK * HD);

    for (int i = tid; i < LTOK * HD; i += 256) {
        sQ[i] = g_Q[base + i];
        int m = i >> 5, d = i & 31;
        sKt[d * SKT_STRIDE + m] = g_K[base + i];
        sV[i] = g_V[base + i];
    }
    // zero Kt padding columns (144..160)
    for (int i = tid; i < 32 * 17; i += 256) {
        int d = i / 17, c = 144 + i % 17;
        sKt[d * SKT_STRIDE + c] = 0.f;
    }
    __syncthreads();

    const int warp = tid >> 5, lane = tid & 31;
    const float* biasrow = g_bias + (size_t)(nw * HEADS + h) * (LTOK * LTOK);
    const float* maskrow = mask + (size_t)b * (LTOK * LTOK);

    for (int it = 0; it < 6; it++) {
        const int l0 = warp * 18 + it * 3;
        float acc[3][5];
#pragma unroll
        for (int j = 0; j < 5; j++) {
            int m = lane + 32 * j;
            if (m < LTOK) {
#pragma unroll
                for (int r = 0; r < 3; r++)
                    acc[r][j] = biasrow[(l0 + r) * LTOK + m] +
                                maskrow[(l0 + r) * LTOK + m];
            } else {
#pragma unroll
                for (int r = 0; r < 3; r++) acc[r][j] = 0.f;
            }
        }
#pragma unroll
        for (int d = 0; d < 32; d++) {
            float q0 = sQ[(l0 + 0) * HD + d];
            float q1 = sQ[(l0 + 1) * HD + d];
            float q2 = sQ[(l0 + 2) * HD + d];
#pragma unroll
            for (int j = 0; j < 5; j++) {
                float kv = sKt[d * SKT_STRIDE + lane + 32 * j];  // padded, safe
                acc[0][j] = fmaf(q0, kv, acc[0][j]);
                acc[1][j] = fmaf(q1, kv, acc[1][j]);
                acc[2][j] = fmaf(q2, kv, acc[2][j]);
            }
        }
        // row-wise softmax (values for m>=144 excluded via guards)
#pragma unroll
        for (int r = 0; r < 3; r++) {
            float mx = -1e30f;
#pragma unroll
            for (int j = 0; j < 5; j++)
                if (lane + 32 * j < LTOK) mx = fmaxf(mx, acc[r][j]);
#pragma unroll
            for (int off = 16; off; off >>= 1)
                mx = fmaxf(mx, __shfl_xor_sync(0xffffffffu, mx, off));
            float e[5];
            float s = 0.f;
#pragma unroll
            for (int j = 0; j < 5; j++) {
                e[j] = (lane + 32 * j < LTOK) ? __expf(acc[r][j] - mx) : 0.f;
                s += e[j];
            }
#pragma unroll
            for (int off = 16; off; off >>= 1)
                s += __shfl_xor_sync(0xffffffffu, s, off);
            float inv = 1.f / s;
#pragma unroll
            for (int j = 0; j < 5; j++) {
                int m = lane + 32 * j;
                if (m < LTOK) sP[(l0 + r) * SP_STRIDE + m] = e[j] * inv;
            }
        }
    }
    __syncthreads();

    // phase 2: O = P @ V  (144 x 32), thread tile 9 rows x 2 cols
    const int ty = tid >> 4;  // 0..15 -> rows ty*9..
    const int tx = tid & 15;  // cols tx*2, tx*2+1
    float o[9][2];
#pragma unroll
    for (int r = 0; r < 9; r++) { o[r][0] = 0.f; o[r][1] = 0.f; }
    for (int m = 0; m < LTOK; m++) {
        float2 v = *reinterpret_cast<const float2*>(&sV[m * HD + tx * 2]);
#pragma unroll
        for (int r = 0; r < 9; r++) {
            float p = sP[(ty * 9 + r) * SP_STRIDE + m];
            o[r][0] = fmaf(p, v.x, o[r][0]);
            o[r][1] = fmaf(p, v.y, o[r][1]);
        }
    }
#pragma unroll
    for (int r = 0; r < 9; r++) {
        int l = ty * 9 + r;
        *reinterpret_cast<float2*>(
            &g_ctx[((size_t)b * LTOK + l) * CDIM + h * HD + tx * 2]) =
            make_float2(o[r][0], o[r][1]);
    }
}

// ---------------------------------------------------------------------------
// K3: out = ctx @ W2 + b2.  Same tiling as K1, N=192.
// ---------------------------------------------------------------------------
__global__ __launch_bounds__(256) void out_gemm_kernel(
    const float* __restrict__ W2, const float* __restrict__ b2,
    float* __restrict__ out) {
    __shared__ float As[16][132];
    __shared__ float Bs[16][64];

    const int tid = threadIdx.x;
    const int tx = tid & 15, ty = tid >> 4;
    const int m_blk = blockIdx.x * 128;
    const int n_blk = blockIdx.y * 64;

    float acc[8][4];
#pragma unroll
    for (int i = 0; i < 8; i++)
#pragma unroll
        for (int j = 0; j < 4; j++) acc[i][j] = 0.f;

    for (int k0 = 0; k0 < CDIM; k0 += 16) {
#pragma unroll
        for (int it = 0; it < 2; it++) {
            int lin = tid + it * 256;
            int row = lin >> 2;
            int cg = (lin & 3) * 4;
            float4 v = *reinterpret_cast<const float4*>(
                &g_ctx[(size_t)(m_blk + row) * CDIM + k0 + cg]);
            As[cg + 0][row] = v.x; As[cg + 1][row] = v.y;
            As[cg + 2][row] = v.z; As[cg + 3][row] = v.w;
        }
        {
            int row = tid >> 4;
            int cg = (tid & 15) * 4;
            *reinterpret_cast<float4*>(&Bs[row][cg]) =
                *reinterpret_cast<const float4*>(
                    &W2[(size_t)(k0 + row) * CDIM + n_blk + cg]);
        }
        __syncthreads();
#pragma unroll
        for (int k = 0; k < 16; k++) {
            float4 a0 = *reinterpret_cast<const float4*>(&As[k][ty * 8]);
            float4 a1 = *reinterpret_cast<const float4*>(&As[k][ty * 8 + 4]);
            float4 bv = *reinterpret_cast<const float4*>(&Bs[k][tx * 4]);
            float a[8] = {a0.x, a0.y, a0.z, a0.w, a1.x, a1.y, a1.z, a1.w};
            float bb[4] = {bv.x, bv.y, bv.z, bv.w};
#pragma unroll
            for (int i = 0; i < 8; i++)
#pragma unroll
                for (int j = 0; j < 4; j++) acc[i][j] = fmaf(a[i], bb[j], acc[i][j]);
        }
        __syncthreads();
    }

#pragma unroll
    for (int i = 0; i < 8; i++) {
        int m = m_blk + ty * 8 + i;
#pragma unroll
        for (int j = 0; j < 4; j++) {
            int col = n_blk + tx * 4 + j;
            out[(size_t)m * CDIM + col] = acc[i][j] + b2[col];
        }
    }
}

// ---------------------------------------------------------------------------
extern "C" void kernel_launch(void* const* d_in, const int* in_sizes, int n_in,
                              void* d_out, int out_size) {
    const float* x     = (const float*)d_in[0];
    const float* mask  = (const float*)d_in[1];
    const float* W1    = (const float*)d_in[2];
    const float* b1    = (const float*)d_in[3];
    const float* W2    = (const float*)d_in[4];
    const float* b2    = (const float*)d_in[5];
    const float* btab  = (const float*)d_in[6];
    const int*   pidx  = (const int*)d_in[7];
    float* out = (float*)d_out;
    (void)in_sizes; (void)n_in; (void)out_size;

    cudaFuncSetAttribute(attn_kernel,
                         cudaFuncAttributeMaxDynamicSharedMemorySize, SMEM_BYTES);

    bias_gather_kernel<<<NW * HEADS, 256>>>(btab, pidx);
    qkv_gemm_kernel<<<dim3(MTOT / 128, 576 / 64), 256>>>(x, W1, b1);
    attn_kernel<<<NWIN * HEADS, 256, SMEM_BYTES>>>(mask);
    out_gemm_kernel<<<dim3(MTOT / 128, CDIM / 64), 256>>>(W2, b2, out);
}

// round 3
// speedup vs baseline: 2.2976x; 2.2976x over previous
#include <cuda_runtime.h>
#include <cuda_bf16.h>
#include <cuda_fp16.h>
#include <cstdint>

// ---------------------------------------------------------------------------
// EarthAttention3D: B_=960, L=144, C=192, H=6, hd=32, NUM_WINDOWS=64, W_WINS=15
// Round 3: mma.sync (legacy HMMA, compute_103-legal) bf16 split GEMMs for
// QKV/output projections; fused fp32 attention with fp16 P buffer.
// ---------------------------------------------------------------------------

#define NWIN   960
#define LTOK   144
#define CDIM   192
#define HEADS  6
#define HD     32
#define NW     64
#define WWINS  15
#define MTOT   (NWIN * LTOK)          // 138240
#define QK_SCALE 0.17677669529663687f

// ------------------------- scratch (device globals) ------------------------
__device__ float g_Q[NWIN * HEADS * LTOK * HD];
__device__ float g_K[NWIN * HEADS * LTOK * HD];
__device__ float g_V[NWIN * HEADS * LTOK * HD];
__device__ float g_bias[NW * HEADS * LTOK * LTOK];
__device__ __nv_bfloat16 g_Xh[MTOT * CDIM];
__device__ __nv_bfloat16 g_Xl[MTOT * CDIM];
__device__ __nv_bfloat16 g_CtxH[MTOT * CDIM];
__device__ __nv_bfloat16 g_CtxL[MTOT * CDIM];
__device__ __nv_bfloat16 g_W1h[576 * 192];
__device__ __nv_bfloat16 g_W1l[576 * 192];
__device__ __nv_bfloat16 g_W2h[192 * 192];
__device__ __nv_bfloat16 g_W2l[192 * 192];

// ------------------------------ helpers ------------------------------------
__device__ __forceinline__ uint32_t smem_u32(const void* p) {
    uint32_t a;
    asm("{ .reg .u64 t; cvta.to.shared.u64 t, %1; cvt.u32.u64 %0, t; }"
        : "=r"(a) : "l"(p));
    return a;
}
__device__ __forceinline__ void bsplit(float v, __nv_bfloat16& h, __nv_bfloat16& l) {
    h = __float2bfloat16(v);
    l = __float2bfloat16(v - __bfloat162float(h));
}

#define LDSM_X4(r0, r1, r2, r3, addr)                                          \
    asm volatile("ldmatrix.sync.aligned.m8n8.x4.shared.b16 {%0,%1,%2,%3}, [%4];" \
                 : "=r"(r0), "=r"(r1), "=r"(r2), "=r"(r3) : "r"(addr))

#define MMA16816(d, a, b)                                                      \
    asm volatile("mma.sync.aligned.m16n8k16.row.col.f32.bf16.bf16.f32 "        \
                 "{%0,%1,%2,%3}, {%4,%5,%6,%7}, {%8,%9}, {%0,%1,%2,%3};"       \
                 : "+f"((d)[0]), "+f"((d)[1]), "+f"((d)[2]), "+f"((d)[3])      \
                 : "r"((a)[0]), "r"((a)[1]), "r"((a)[2]), "r"((a)[3]),         \
                   "r"((b)[0]), "r"((b)[1]))

// ---------------------------------------------------------------------------
// Prep: fp32 -> bf16 hi/lo splits
// ---------------------------------------------------------------------------
__global__ void splitX_kernel(const float* __restrict__ x,
                              __nv_bfloat16* __restrict__ h,
                              __nv_bfloat16* __restrict__ l, int n4) {
    int i = blockIdx.x * blockDim.x + threadIdx.x;
    if (i >= n4) return;
    float4 v = reinterpret_cast<const float4*>(x)[i];
    __nv_bfloat16 h0, h1, h2, h3, l0, l1, l2, l3;
    bsplit(v.x, h0, l0); bsplit(v.y, h1, l1);
    bsplit(v.z, h2, l2); bsplit(v.w, h3, l3);
    reinterpret_cast<__nv_bfloat162*>(h)[2 * i]     = __halves2bfloat162(h0, h1);
    reinterpret_cast<__nv_bfloat162*>(h)[2 * i + 1] = __halves2bfloat162(h2, h3);
    reinterpret_cast<__nv_bfloat162*>(l)[2 * i]     = __halves2bfloat162(l0, l1);
    reinterpret_cast<__nv_bfloat162*>(l)[2 * i + 1] = __halves2bfloat162(l2, l3);
}

// W [K=192][N] fp32 -> Bt [N][192] bf16 hi/lo (K-contiguous rows)
__global__ void splitW_kernel(const float* __restrict__ W,
                              __nv_bfloat16* __restrict__ h,
                              __nv_bfloat16* __restrict__ l, int N) {
    int idx = blockIdx.x * blockDim.x + threadIdx.x;
    if (idx >= N * 192) return;
    int n = idx / 192, k = idx - n * 192;
    __nv_bfloat16 hh, ll;
    bsplit(W[(size_t)k * N + n], hh, ll);
    h[idx] = hh; l[idx] = ll;
}

// ---------------------------------------------------------------------------
// K0: bias gather
// ---------------------------------------------------------------------------
__global__ void bias_gather_kernel(const float* __restrict__ table,
                                   const int* __restrict__ pidx) {
    const int nwh = blockIdx.x;
    const int nw = nwh / HEADS, h = nwh % HEADS;
    float* dst = g_bias + (size_t)nwh * (LTOK * LTOK);
    for (int i = threadIdx.x; i < LTOK * LTOK; i += blockDim.x) {
        int pi = pidx[i];
        dst[i] = table[((size_t)pi * NW + nw) * HEADS + h];
    }
}

// ---------------------------------------------------------------------------
// Split-bf16 GEMM via mma.sync: C[M, Ntot] = A[M,192] @ Bt[Ntot,192]^T + bias
//   CTA: 128 M-rows (A hi/lo resident in SMEM), loops ntiles N-tiles of 64.
//   8 warps (4m x 2n), warp tile 32x32, m16n8k16, 3 split passes.
//   mode 0 -> scatter Q(scaled)/K/V head-major; mode 1 -> out[M,192].
// ---------------------------------------------------------------------------
#define ASTR 200                       // bf16 row stride (400 B, ldmatrix-safe)
#define GEMM_SMEM ((2 * 128 * ASTR + 2 * 64 * ASTR) * 2)  // 153600 B

__global__ __launch_bounds__(256) void mma_gemm_kernel(
    const __nv_bfloat16* __restrict__ Ah, const __nv_bfloat16* __restrict__ Al,
    const __nv_bfloat16* __restrict__ Bh, const __nv_bfloat16* __restrict__ Bl,
    const float* __restrict__ bias, int ntiles, int mode,
    float* __restrict__ out) {
    extern __shared__ __align__(16) __nv_bfloat16 sb[];
    __nv_bfloat16* sAh = sb;                       // [128][ASTR]
    __nv_bfloat16* sAl = sb + 128 * ASTR;
    __nv_bfloat16* sBh = sb + 2 * 128 * ASTR;      // [64][ASTR]
    __nv_bfloat16* sBl = sBh + 64 * ASTR;

    const int tid = threadIdx.x;
    const int warp = tid >> 5, lane = tid & 31;
    const int warpm = warp >> 1, warpn = warp & 1;
    const int m_blk = blockIdx.x * 128;

    // ---- stage A tile (hi+lo) ----
    for (int i = tid; i < 128 * 24; i += 256) {
        int r = i / 24, c = (i % 24) * 8;
        *reinterpret_cast<uint4*>(&sAh[r * ASTR + c]) =
            *reinterpret_cast<const uint4*>(&Ah[(size_t)(m_blk + r) * 192 + c]);
        *reinterpret_cast<uint4*>(&sAl[r * ASTR + c]) =
            *reinterpret_cast<const uint4*>(&Al[(size_t)(m_blk + r) * 192 + c]);
    }
    __syncthreads();

    const int lr = lane & 7, sel = lane >> 3;
    // A ldmatrix: row = mbase + lr + (sel&1)*8, col = k0 + (sel>>1)*8
    const int a_row_off = lr + (sel & 1) * 8;
    const int a_col_off = (sel >> 1) * 8;
    // B ldmatrix: row = nbase + lr + (sel>>1)*8, col = k0 + (sel&1)*8
    const int b_row_off = lr + (sel >> 1) * 8;
    const int b_col_off = (sel & 1) * 8;

    for (int nt = 0; nt < ntiles; nt++) {
        // ---- stage B tile (hi+lo) ----
        for (int i = tid; i < 64 * 24; i += 256) {
            int r = i / 24, c = (i % 24) * 8;
            *reinterpret_cast<uint4*>(&sBh[r * ASTR + c]) =
                *reinterpret_cast<const uint4*>(&Bh[(size_t)(nt * 64 + r) * 192 + c]);
            *reinterpret_cast<uint4*>(&sBl[r * ASTR + c]) =
                *reinterpret_cast<const uint4*>(&Bl[(size_t)(nt * 64 + r) * 192 + c]);
        }
        __syncthreads();

        float acc[2][4][4];
#pragma unroll
        for (int mt = 0; mt < 2; mt++)
#pragma unroll
            for (int t4 = 0; t4 < 4; t4++)
#pragma unroll
                for (int j = 0; j < 4; j++) acc[mt][t4][j] = 0.f;

#pragma unroll 4
        for (int ks = 0; ks < 12; ks++) {
            const int k0 = ks * 16;
            uint32_t ah[2][4], al[2][4], bh[4][2], bl[4][2];
#pragma unroll
            for (int mt = 0; mt < 2; mt++) {
                int row = warpm * 32 + mt * 16 + a_row_off;
                uint32_t ad = smem_u32(&sAh[row * ASTR + k0 + a_col_off]);
                LDSM_X4(ah[mt][0], ah[mt][1], ah[mt][2], ah[mt][3], ad);
                uint32_t ad2 = smem_u32(&sAl[row * ASTR + k0 + a_col_off]);
                LDSM_X4(al[mt][0], al[mt][1], al[mt][2], al[mt][3], ad2);
            }
#pragma unroll
            for (int pr = 0; pr < 2; pr++) {
                int row = warpn * 32 + pr * 16 + b_row_off;
                uint32_t bd = smem_u32(&sBh[row * ASTR + k0 + b_col_off]);
                LDSM_X4(bh[2 * pr][0], bh[2 * pr][1], bh[2 * pr + 1][0],
                        bh[2 * pr + 1][1], bd);
                uint32_t bd2 = smem_u32(&sBl[row * ASTR + k0 + b_col_off]);
                LDSM_X4(bl[2 * pr][0], bl[2 * pr][1], bl[2 * pr + 1][0],
                        bl[2 * pr + 1][1], bd2);
            }
#pragma unroll
            for (int mt = 0; mt < 2; mt++)
#pragma unroll
                for (int t4 = 0; t4 < 4; t4++) {
                    MMA16816(acc[mt][t4], ah[mt], bh[t4]);
                    MMA16816(acc[mt][t4], al[mt], bh[t4]);
                    MMA16816(acc[mt][t4], ah[mt], bl[t4]);
                }
        }

        // ---- epilogue ----
        const int qrow = lane >> 2;
        const int qcol = (lane & 3) * 2;
#pragma unroll
        for (int mt = 0; mt < 2; mt++) {
#pragma unroll
            for (int t4 = 0; t4 < 4; t4++) {
                const int col = nt * 64 + warpn * 32 + t4 * 8 + qcol;
                const float b0 = bias[col], b1 = bias[col + 1];
                const int r0 = m_blk + warpm * 32 + mt * 16 + qrow;
                float v00 = acc[mt][t4][0] + b0, v01 = acc[mt][t4][1] + b1;
                float v10 = acc[mt][t4][2] + b0, v11 = acc[mt][t4][3] + b1;
                if (mode == 1) {
                    *reinterpret_cast<float2*>(&out[(size_t)r0 * CDIM + col]) =
                        make_float2(v00, v01);
                    *reinterpret_cast<float2*>(&out[(size_t)(r0 + 8) * CDIM + col]) =
                        make_float2(v10, v11);
                } else {
                    const int t = col / CDIM;
                    const int rem = col - t * CDIM;
                    const int hh = rem >> 5, dd = rem & 31;
                    const int bi0 = r0 / LTOK, l0 = r0 - bi0 * LTOK;
                    const int r1 = r0 + 8;
                    const int bi1 = r1 / LTOK, l1 = r1 - bi1 * LTOK;
                    const size_t o0 = ((size_t)(bi0 * HEADS + hh) * LTOK + l0) * HD + dd;
                    const size_t o1 = ((size_t)(bi1 * HEADS + hh) * LTOK + l1) * HD + dd;
                    if (t == 0) {
                        *reinterpret_cast<float2*>(g_Q + o0) =
                            make_float2(v00 * QK_SCALE, v01 * QK_SCALE);
                        *reinterpret_cast<float2*>(g_Q + o1) =
                            make_float2(v10 * QK_SCALE, v11 * QK_SCALE);
                    } else if (t == 1) {
                        *reinterpret_cast<float2*>(g_K + o0) = make_float2(v00, v01);
                        *reinterpret_cast<float2*>(g_K + o1) = make_float2(v10, v11);
                    } else {
                        *reinterpret_cast<float2*>(g_V + o0) = make_float2(v00, v01);
                        *reinterpret_cast<float2*>(g_V + o1) = make_float2(v10, v11);
                    }
                }
            }
        }
        __syncthreads();
    }
}

// ---------------------------------------------------------------------------
// K2: fused attention per (window, head). 256 threads, fp16 P (2 CTA/SM).
// ---------------------------------------------------------------------------
#define SKT_STRIDE 161
#define SPH 146
#define SMEM_BYTES ((4608 + 32 * SKT_STRIDE + 4608) * 4 + LTOK * SPH * 2)

__global__ __launch_bounds__(256) void attn_kernel(const float* __restrict__ mask) {
    extern __shared__ float sm[];
    float* sQ = sm;                               // [144][32]
    float* sKt = sm + 4608;                       // [32][161]
    float* sV = sKt + 32 * SKT_STRIDE;            // [144][32]
    __half* sP = reinterpret_cast<__half*>(sV + 4608);  // [144][146]

    const int bh = blockIdx.x;
    const int b = bh / HEADS, h = bh % HEADS;
    const int nw = b / WWINS;
    const int tid = threadIdx.x;
    const size_t base = (size_t)bh * (LTOK * HD);

    for (int i = tid; i < LTOK * HD; i += 256) {
        sQ[i] = g_Q[base + i];
        int m = i >> 5, d = i & 31;
        sKt[d * SKT_STRIDE + m] = g_K[base + i];
        sV[i] = g_V[base + i];
    }
    for (int i = tid; i < 32 * 17; i += 256) {
        int d = i / 17, c = 144 + i % 17;
        sKt[d * SKT_STRIDE + c] = 0.f;
    }
    __syncthreads();

    const int warp = tid >> 5, lane = tid & 31;
    const float* biasrow = g_bias + (size_t)(nw * HEADS + h) * (LTOK * LTOK);
    const float* maskrow = mask + (size_t)b * (LTOK * LTOK);

    for (int it = 0; it < 6; it++) {
        const int l0 = warp * 18 + it * 3;
        float acc[3][5];
#pragma unroll
        for (int j = 0; j < 5; j++) {
            int m = lane + 32 * j;
            if (m < LTOK) {
#pragma unroll
                for (int r = 0; r < 3; r++)
                    acc[r][j] = biasrow[(l0 + r) * LTOK + m] +
                                maskrow[(l0 + r) * LTOK + m];
            } else {
#pragma unroll
                for (int r = 0; r < 3; r++) acc[r][j] = 0.f;
            }
        }
#pragma unroll
        for (int d = 0; d < 32; d++) {
            float q0 = sQ[(l0 + 0) * HD + d];
            float q1 = sQ[(l0 + 1) * HD + d];
            float q2 = sQ[(l0 + 2) * HD + d];
#pragma unroll
            for (int j = 0; j < 5; j++) {
                float kv = sKt[d * SKT_STRIDE + lane + 32 * j];
                acc[0][j] = fmaf(q0, kv, acc[0][j]);
                acc[1][j] = fmaf(q1, kv, acc[1][j]);
                acc[2][j] = fmaf(q2, kv, acc[2][j]);
            }
        }
#pragma unroll
        for (int r = 0; r < 3; r++) {
            float mx = -1e30f;
#pragma unroll
            for (int j = 0; j < 5; j++)
                if (lane + 32 * j < LTOK) mx = fmaxf(mx, acc[r][j]);
#pragma unroll
            for (int off = 16; off; off >>= 1)
                mx = fmaxf(mx, __shfl_xor_sync(0xffffffffu, mx, off));
            float e[5];
            float s = 0.f;
#pragma unroll
            for (int j = 0; j < 5; j++) {
                e[j] = (lane + 32 * j < LTOK) ? __expf(acc[r][j] - mx) : 0.f;
                s += e[j];
            }
#pragma unroll
            for (int off = 16; off; off >>= 1)
                s += __shfl_xor_sync(0xffffffffu, s, off);
            float inv = 1.f / s;
#pragma unroll
            for (int j = 0; j < 5; j++) {
                int m = lane + 32 * j;
                if (m < LTOK) sP[(l0 + r) * SPH + m] = __float2half(e[j] * inv);
            }
        }
    }
    __syncthreads();

    // phase 2: O = P @ V, write bf16-split ctx for the output GEMM
    const int ty = tid >> 4;
    const int tx = tid & 15;
    float o[9][2];
#pragma unroll
    for (int r = 0; r < 9; r++) { o[r][0] = 0.f; o[r][1] = 0.f; }
    for (int m = 0; m < LTOK; m++) {
        float2 v = *reinterpret_cast<const float2*>(&sV[m * HD + tx * 2]);
#pragma unroll
        for (int r = 0; r < 9; r++) {
            float p = __half2float(sP[(ty * 9 + r) * SPH + m]);
            o[r][0] = fmaf(p, v.x, o[r][0]);
            o[r][1] = fmaf(p, v.y, o[r][1]);
        }
    }
#pragma unroll
    for (int r = 0; r < 9; r++) {
        int l = ty * 9 + r;
        size_t off = ((size_t)b * LTOK + l) * CDIM + h * HD + tx * 2;
        __nv_bfloat16 h0, h1, l0b, l1b;
        bsplit(o[r][0], h0, l0b);
        bsplit(o[r][1], h1, l1b);
        *reinterpret_cast<__nv_bfloat162*>(g_CtxH + off) = __halves2bfloat162(h0, h1);
        *reinterpret_cast<__nv_bfloat162*>(g_CtxL + off) = __halves2bfloat162(l0b, l1b);
    }
}

// ---------------------------------------------------------------------------
extern "C" void kernel_launch(void* const* d_in, const int* in_sizes, int n_in,
                              void* d_out, int out_size) {
    const float* x    = (const float*)d_in[0];
    const float* mask = (const float*)d_in[1];
    const float* W1   = (const float*)d_in[2];
    const float* b1   = (const float*)d_in[3];
    const float* W2   = (const float*)d_in[4];
    const float* b2   = (const float*)d_in[5];
    const float* btab = (const float*)d_in[6];
    const int*   pidx = (const int*)d_in[7];
    float* out = (float*)d_out;
    (void)in_sizes; (void)n_in; (void)out_size;

    cudaFuncSetAttribute(mma_gemm_kernel,
                         cudaFuncAttributeMaxDynamicSharedMemorySize, GEMM_SMEM);
    cudaFuncSetAttribute(attn_kernel,
                         cudaFuncAttributeMaxDynamicSharedMemorySize, SMEM_BYTES);

    __nv_bfloat16 *xh, *xl, *ch, *cl, *w1h, *w1l, *w2h, *w2l;
    cudaGetSymbolAddress((void**)&xh, g_Xh);
    cudaGetSymbolAddress((void**)&xl, g_Xl);
    cudaGetSymbolAddress((void**)&ch, g_CtxH);
    cudaGetSymbolAddress((void**)&cl, g_CtxL);
    cudaGetSymbolAddress((void**)&w1h, g_W1h);
    cudaGetSymbolAddress((void**)&w1l, g_W1l);
    cudaGetSymbolAddress((void**)&w2h, g_W2h);
    cudaGetSymbolAddress((void**)&w2l, g_W2l);

    const int n4 = MTOT * CDIM / 4;
    splitX_kernel<<<(n4 + 255) / 256, 256>>>(x, xh, xl, n4);
    splitW_kernel<<<(576 * 192 + 255) / 256, 256>>>(W1, w1h, w1l, 576);
    splitW_kernel<<<(192 * 192 + 255) / 256, 256>>>(W2, w2h, w2l, 192);
    bias_gather_kernel<<<NW * HEADS, 256>>>(btab, pidx);

    mma_gemm_kernel<<<MTOT / 128, 256, GEMM_SMEM>>>(xh, xl, w1h, w1l, b1, 9, 0, nullptr);
    attn_kernel<<<NWIN * HEADS, 256, SMEM_BYTES>>>(mask);
    mma_gemm_kernel<<<MTOT / 128, 256, GEMM_SMEM>>>(ch, cl, w2h, w2l, b2, 3, 1, out);
}